// round 5
// baseline (speedup 1.0000x reference)
#include <cuda_runtime.h>
#include <cuda_bf16.h>
#include <cstdint>

// ---------------------------------------------------------------------------
// Problem constants (fixed by setup_inputs)
// ---------------------------------------------------------------------------
#define BSZ     4
#define QLEN    1024
#define DEMB    768
#define DMODEL  1024
#define NHEAD   16
#define DHEAD   64
#define M_ROWS  (QLEN*BSZ)          // 4096, row r = q*4 + b
#define H3      (3*NHEAD*DHEAD)     // 3072
#define SCALE   (0.125f)            // 1/sqrt(64)

// ---------------------------------------------------------------------------
// Scratch (device globals; no allocation allowed)
// ---------------------------------------------------------------------------
__device__ float g_h[M_ROWS * DMODEL];            // 16 MB  (h, also attn_vec of MHA0)
__device__ float g_heads[M_ROWS * H3];            // 48 MB  (QKV projections)
__device__ float g_P[64u * 1024u * 1024u];        // 256 MB (attn_prob scratch, [bn][i][j])

// ---------------------------------------------------------------------------
// Helpers
// ---------------------------------------------------------------------------
__device__ __forceinline__ uint32_t f2tf(float f) {
    uint32_t u;
    asm("cvt.rna.tf32.f32 %0, %1;" : "=r"(u) : "f"(f));
    return u;
}

__device__ __forceinline__ void mma_tf32(float c[4],
                                         uint32_t a0, uint32_t a1, uint32_t a2, uint32_t a3,
                                         uint32_t b0, uint32_t b1) {
    asm volatile(
        "mma.sync.aligned.m16n8k8.row.col.f32.tf32.tf32.f32 "
        "{%0,%1,%2,%3}, {%4,%5,%6,%7}, {%8,%9}, {%0,%1,%2,%3};"
        : "+f"(c[0]), "+f"(c[1]), "+f"(c[2]), "+f"(c[3])
        : "r"(a0), "r"(a1), "r"(a2), "r"(a3), "r"(b0), "r"(b1));
}

// ---------------------------------------------------------------------------
// TF32 GEMM: C[M_ROWS, N] = A @ B (+bias)
//   AMODE 0: A is word_emb, A[r][k] = word_emb[(r&3)*QLEN*DEMB + (r>>2)*DEMB + k]
//   AMODE 1: A row-major [M_ROWS, K]
// BM=128, BN=128, BK=16, 256 threads (8 warps), warp tile 64x32, mma m16n8k8.
// ---------------------------------------------------------------------------
template<int AMODE, int K, int N>
__global__ __launch_bounds__(256, 2)
void gemm_tf32(const float* __restrict__ A, const float* __restrict__ B,
               const float* __restrict__ bias, float* __restrict__ C)
{
    __shared__ uint32_t As[128][17];   // [m][k]
    __shared__ uint32_t Bs[16][132];   // [k][n]

    const int t    = threadIdx.x;
    const int lane = t & 31;
    const int w    = t >> 5;
    const int wm   = w >> 2;   // 0..1  (64 rows each)
    const int wn   = w & 3;    // 0..3  (32 cols each)
    const int mblk = blockIdx.y;
    const int nblk = blockIdx.x;

    float acc[4][4][4];
    #pragma unroll
    for (int im = 0; im < 4; im++)
        #pragma unroll
        for (int in = 0; in < 4; in++)
            #pragma unroll
            for (int j = 0; j < 4; j++) acc[im][in][j] = 0.f;

    const int KT = K / 16;

    // register prefetch buffers: A 2 x float4, B 2 x float4
    float4 ra[2], rb[2];

    // --- load tile kt into registers ---
    auto loadA = [&](int kt, float4 r[2]) {
        #pragma unroll
        for (int it = 0; it < 2; it++) {
            int idx = t + it * 256;            // 0..511
            int m   = idx >> 2;                // 0..127
            int k4  = idx & 3;                 // 0..3
            int gk  = kt * 16 + k4 * 4;
            int mg  = mblk * 128 + m;
            long off;
            if (AMODE == 0)
                off = (long)((mg & 3) * QLEN + (mg >> 2)) * DEMB + gk;
            else
                off = (long)mg * K + gk;
            r[it] = *(const float4*)(A + off);
        }
    };
    auto loadB = [&](int kt, float4 r[2]) {
        #pragma unroll
        for (int it = 0; it < 2; it++) {
            int idx = t + it * 256;            // 0..511
            int k   = idx >> 5;                // 0..15
            int n4  = idx & 31;                // 0..31
            r[it] = *(const float4*)(B + (long)(kt * 16 + k) * N + nblk * 128 + n4 * 4);
        }
    };

    loadA(0, ra);
    loadB(0, rb);

    for (int kt = 0; kt < KT; kt++) {
        __syncthreads();   // previous compute done; smem free
        // store prefetched regs -> smem (convert to tf32)
        #pragma unroll
        for (int it = 0; it < 2; it++) {
            int idx = t + it * 256;
            int m = idx >> 2, k4 = idx & 3;
            As[m][k4 * 4 + 0] = f2tf(ra[it].x);
            As[m][k4 * 4 + 1] = f2tf(ra[it].y);
            As[m][k4 * 4 + 2] = f2tf(ra[it].z);
            As[m][k4 * 4 + 3] = f2tf(ra[it].w);
        }
        #pragma unroll
        for (int it = 0; it < 2; it++) {
            int idx = t + it * 256;
            int k = idx >> 5, n4 = idx & 31;
            Bs[k][n4 * 4 + 0] = f2tf(rb[it].x);
            Bs[k][n4 * 4 + 1] = f2tf(rb[it].y);
            Bs[k][n4 * 4 + 2] = f2tf(rb[it].z);
            Bs[k][n4 * 4 + 3] = f2tf(rb[it].w);
        }
        __syncthreads();
        if (kt + 1 < KT) { loadA(kt + 1, ra); loadB(kt + 1, rb); }

        // compute on smem tile
        #pragma unroll
        for (int ks = 0; ks < 2; ks++) {
            const int ka = ks * 8 + (lane & 3);
            uint32_t bf[4][2];
            #pragma unroll
            for (int in = 0; in < 4; in++) {
                int col = wn * 32 + in * 8 + (lane >> 2);
                bf[in][0] = Bs[ka][col];
                bf[in][1] = Bs[ka + 4][col];
            }
            #pragma unroll
            for (int im = 0; im < 4; im++) {
                int row = wm * 64 + im * 16 + (lane >> 2);
                uint32_t a0 = As[row][ka];
                uint32_t a1 = As[row + 8][ka];
                uint32_t a2 = As[row][ka + 4];
                uint32_t a3 = As[row + 8][ka + 4];
                #pragma unroll
                for (int in = 0; in < 4; in++)
                    mma_tf32(acc[im][in], a0, a1, a2, a3, bf[in][0], bf[in][1]);
            }
        }
    }

    // epilogue
    #pragma unroll
    for (int im = 0; im < 4; im++) {
        #pragma unroll
        for (int in = 0; in < 4; in++) {
            int r0 = mblk * 128 + wm * 64 + im * 16 + (lane >> 2);
            int c0 = nblk * 128 + wn * 32 + in * 8 + 2 * (lane & 3);
            float b0v = 0.f, b1v = 0.f;
            if (bias) { b0v = bias[c0]; b1v = bias[c0 + 1]; }
            C[(long)r0 * N + c0]           = acc[im][in][0] + b0v;
            C[(long)r0 * N + c0 + 1]       = acc[im][in][1] + b1v;
            C[(long)(r0 + 8) * N + c0]     = acc[im][in][2] + b0v;
            C[(long)(r0 + 8) * N + c0 + 1] = acc[im][in][3] + b1v;
        }
    }
}

// ---------------------------------------------------------------------------
// Fused attention: one CTA = (bn = b*16+n, 32-row q tile).
// S tile (32x1024 fp32) in shared memory; exact softmax; TF32 mma for both GEMMs.
// Writes attn_vec to outp[r*1024 + n*64 + d] (r = q*4+b).
// If Pout != nullptr: writes normalized probs to Pout[bn*1M + i*1024 + j].
// ---------------------------------------------------------------------------
#define SSM_LD 1028
#define QK_LD  68
#define ATTN_SMEM_BYTES ((32*SSM_LD + 32*QK_LD + 64*QK_LD) * 4)

__global__ __launch_bounds__(256, 1)
void attn_kernel(const float* __restrict__ heads, float* __restrict__ outp,
                 float* __restrict__ Pout)
{
    extern __shared__ float sm[];
    float*    Ssm = sm;                                   // [32][1028] fp32
    uint32_t* Qsm = (uint32_t*)(sm + 32 * SSM_LD);        // [32][68]   tf32
    uint32_t* KV  = Qsm + 32 * QK_LD;                     // [64][68]   tf32

    const int t    = threadIdx.x;
    const int lane = t & 31;
    const int w    = t >> 5;
    const int wm   = w >> 2;   // 0..1
    const int wn   = w & 3;    // 0..3
    const int bn   = blockIdx.x;     // 0..63
    const int qt   = blockIdx.y;     // 0..31
    const int b    = bn >> 4;
    const int n    = bn & 15;

    // ---- load Q tile (32 x 64) ----
    #pragma unroll
    for (int it = 0; it < 2; it++) {
        int idx = t + it * 256;           // 0..511
        int ir = idx >> 4, d4 = idx & 15;
        const float4 q = *(const float4*)(heads +
            (long)((qt * 32 + ir) * 4 + b) * H3 + n * 64 + d4 * 4);
        uint32_t* dst = Qsm + ir * QK_LD + d4 * 4;
        dst[0] = f2tf(q.x); dst[1] = f2tf(q.y); dst[2] = f2tf(q.z); dst[3] = f2tf(q.w);
    }

    // ---- S = Q K^T * SCALE, streamed over 16 j-tiles of 64 ----
    for (int jt = 0; jt < 16; jt++) {
        #pragma unroll
        for (int it = 0; it < 4; it++) {
            int idx = t + it * 256;       // 0..1023
            int jj = idx >> 4, d4 = idx & 15;
            const float4 kv = *(const float4*)(heads +
                (long)((jt * 64 + jj) * 4 + b) * H3 + DMODEL + n * 64 + d4 * 4);
            uint32_t* dst = KV + jj * QK_LD + d4 * 4;
            dst[0] = f2tf(kv.x); dst[1] = f2tf(kv.y); dst[2] = f2tf(kv.z); dst[3] = f2tf(kv.w);
        }
        __syncthreads();

        float sacc[2][4] = {};
        #pragma unroll
        for (int ks = 0; ks < 8; ks++) {
            const int ka  = ks * 8 + (lane & 3);
            const int row = wm * 16 + (lane >> 2);
            uint32_t a0 = Qsm[row * QK_LD + ka];
            uint32_t a1 = Qsm[(row + 8) * QK_LD + ka];
            uint32_t a2 = Qsm[row * QK_LD + ka + 4];
            uint32_t a3 = Qsm[(row + 8) * QK_LD + ka + 4];
            #pragma unroll
            for (int in = 0; in < 2; in++) {
                int jl = wn * 16 + in * 8 + (lane >> 2);
                uint32_t b0 = KV[jl * QK_LD + ka];
                uint32_t b1 = KV[jl * QK_LD + ka + 4];
                mma_tf32(sacc[in], a0, a1, a2, a3, b0, b1);
            }
        }
        #pragma unroll
        for (int in = 0; in < 2; in++) {
            int r = wm * 16 + (lane >> 2);
            int c = jt * 64 + wn * 16 + in * 8 + 2 * (lane & 3);
            Ssm[r * SSM_LD + c]             = sacc[in][0] * SCALE;
            Ssm[r * SSM_LD + c + 1]         = sacc[in][1] * SCALE;
            Ssm[(r + 8) * SSM_LD + c]       = sacc[in][2] * SCALE;
            Ssm[(r + 8) * SSM_LD + c + 1]   = sacc[in][3] * SCALE;
        }
        __syncthreads();
    }

    // ---- exact softmax over full 1024-row (one warp per row, 4 rows/warp) ----
    for (int rr = 0; rr < 4; rr++) {
        const int r = w * 4 + rr;
        float vals[32];
        float mx = -1e30f;
        #pragma unroll
        for (int c = 0; c < 32; c++) {
            vals[c] = Ssm[r * SSM_LD + c * 32 + lane];
            mx = fmaxf(mx, vals[c]);
        }
        #pragma unroll
        for (int o = 16; o; o >>= 1) mx = fmaxf(mx, __shfl_xor_sync(0xffffffffu, mx, o));
        float s = 0.f;
        #pragma unroll
        for (int c = 0; c < 32; c++) { vals[c] = __expf(vals[c] - mx); s += vals[c]; }
        #pragma unroll
        for (int o = 16; o; o >>= 1) s += __shfl_xor_sync(0xffffffffu, s, o);
        const float inv = 1.f / s;
        const int gi = qt * 32 + r;
        #pragma unroll
        for (int c = 0; c < 32; c++) {
            float p = vals[c] * inv;
            Ssm[r * SSM_LD + c * 32 + lane] = p;
            if (Pout)
                Pout[(size_t)bn * 1048576 + (size_t)gi * 1024 + c * 32 + lane] = p;
        }
    }
    __syncthreads();

    // ---- O = P V, streamed over 16 j-tiles of 64 ----
    float oacc[2][4] = {};
    for (int jt = 0; jt < 16; jt++) {
        #pragma unroll
        for (int it = 0; it < 4; it++) {
            int idx = t + it * 256;
            int jj = idx >> 4, d4 = idx & 15;
            const float4 v = *(const float4*)(heads +
                (long)((jt * 64 + jj) * 4 + b) * H3 + 2 * DMODEL + n * 64 + d4 * 4);
            uint32_t* dst = KV + jj * QK_LD + d4 * 4;
            dst[0] = f2tf(v.x); dst[1] = f2tf(v.y); dst[2] = f2tf(v.z); dst[3] = f2tf(v.w);
        }
        __syncthreads();

        #pragma unroll
        for (int ks = 0; ks < 8; ks++) {
            const int row = wm * 16 + (lane >> 2);
            const int kc  = jt * 64 + ks * 8 + (lane & 3);
            uint32_t a0 = f2tf(Ssm[row * SSM_LD + kc]);
            uint32_t a1 = f2tf(Ssm[(row + 8) * SSM_LD + kc]);
            uint32_t a2 = f2tf(Ssm[row * SSM_LD + kc + 4]);
            uint32_t a3 = f2tf(Ssm[(row + 8) * SSM_LD + kc + 4]);
            const int kb = ks * 8 + (lane & 3);
            #pragma unroll
            for (int in = 0; in < 2; in++) {
                int dl = wn * 16 + in * 8 + (lane >> 2);
                uint32_t b0 = KV[kb * QK_LD + dl];
                uint32_t b1 = KV[(kb + 4) * QK_LD + dl];
                mma_tf32(oacc[in], a0, a1, a2, a3, b0, b1);
            }
        }
        __syncthreads();
    }

    // ---- epilogue: out[r=(i*4+b)][n*64 + d] ----
    #pragma unroll
    for (int in = 0; in < 2; in++) {
        int r  = wm * 16 + (lane >> 2);
        int c  = n * 64 + wn * 16 + in * 8 + 2 * (lane & 3);
        long gr0 = (long)((qt * 32 + r) * 4 + b);
        long gr1 = (long)((qt * 32 + r + 8) * 4 + b);
        outp[gr0 * DMODEL + c]     = oacc[in][0];
        outp[gr0 * DMODEL + c + 1] = oacc[in][1];
        outp[gr1 * DMODEL + c]     = oacc[in][2];
        outp[gr1 * DMODEL + c + 1] = oacc[in][3];
    }
}

// ---------------------------------------------------------------------------
// Reformat P scratch [bn][i][j] -> out [i][j][b][n]  (bn = b*16+n fastest dim)
// One CTA per (jc, i): moves a [64 j] x [64 bn] tile via smem transpose.
// ---------------------------------------------------------------------------
__global__ __launch_bounds__(256)
void transpose_P(const float* __restrict__ P, float* __restrict__ out)
{
    __shared__ float T[64][65];
    const int jc = blockIdx.x;   // 0..15
    const int i  = blockIdx.y;   // 0..1023
    const int t  = threadIdx.x;

    #pragma unroll
    for (int it = 0; it < 4; it++) {
        int idx = t + it * 256;            // 0..1023
        int bnv = idx >> 4, j4 = idx & 15;
        float4 v = *(const float4*)(P + (size_t)bnv * 1048576 + (size_t)i * 1024 + jc * 64 + j4 * 4);
        T[j4 * 4 + 0][bnv] = v.x;
        T[j4 * 4 + 1][bnv] = v.y;
        T[j4 * 4 + 2][bnv] = v.z;
        T[j4 * 4 + 3][bnv] = v.w;
    }
    __syncthreads();
    #pragma unroll
    for (int it = 0; it < 4; it++) {
        int idx = t + it * 256;
        int jv = idx >> 4, b4 = idx & 15;
        float4 v = make_float4(T[jv][b4 * 4], T[jv][b4 * 4 + 1],
                               T[jv][b4 * 4 + 2], T[jv][b4 * 4 + 3]);
        *(float4*)(out + (size_t)i * 65536 + (size_t)(jc * 64 + jv) * 64 + b4 * 4) = v;
    }
}

// ---------------------------------------------------------------------------
// Launch
// ---------------------------------------------------------------------------
extern "C" void kernel_launch(void* const* d_in, const int* in_sizes, int n_in,
                              void* d_out, int out_size)
{
    const float* word_emb = (const float*)d_in[0];   // [4,1024,768]
    const float* emb_w    = (const float*)d_in[1];   // [768,1024]
    const float* emb_b    = (const float*)d_in[2];   // [1024]
    const float* qkv_w0   = (const float*)d_in[3];   // [1024,3072]
    const float* qkv_w1   = (const float*)d_in[4];   // [1024,3072]

    float* core_out = (float*)d_out;                         // [1024,4,1024]
    float* attn_out = (float*)d_out + (size_t)M_ROWS * DMODEL; // [1024,1024,4,16]

    float *h, *heads, *P;
    cudaGetSymbolAddress((void**)&h,     g_h);
    cudaGetSymbolAddress((void**)&heads, g_heads);
    cudaGetSymbolAddress((void**)&P,     g_P);

    cudaFuncSetAttribute(attn_kernel,
                         cudaFuncAttributeMaxDynamicSharedMemorySize,
                         ATTN_SMEM_BYTES);

    // 1) h = transpose(word_emb) @ emb_w + emb_b
    gemm_tf32<0, DEMB, DMODEL><<<dim3(DMODEL / 128, M_ROWS / 128), 256>>>(
        word_emb, emb_w, emb_b, h);

    // 2) MHA #0
    gemm_tf32<1, DMODEL, H3><<<dim3(H3 / 128, M_ROWS / 128), 256>>>(
        h, qkv_w0, nullptr, heads);
    attn_kernel<<<dim3(64, 32), 256, ATTN_SMEM_BYTES>>>(heads, h, nullptr);

    // 3) MHA #1 (attn maps kept)
    gemm_tf32<1, DMODEL, H3><<<dim3(H3 / 128, M_ROWS / 128), 256>>>(
        h, qkv_w1, nullptr, heads);
    attn_kernel<<<dim3(64, 32), 256, ATTN_SMEM_BYTES>>>(heads, core_out, P);

    // 4) attn_prob reformat [bn][i][j] -> [i][j][b][n]
    transpose_P<<<dim3(16, 1024), 256>>>(P, attn_out);
}

// round 6
// speedup vs baseline: 1.7453x; 1.7453x over previous
#include <cuda_runtime.h>
#include <cuda_fp16.h>
#include <cstdint>

// ---------------------------------------------------------------------------
// Problem constants
// ---------------------------------------------------------------------------
#define BSZ     4
#define QLEN    1024
#define DEMB    768
#define DMODEL  1024
#define NHEAD   16
#define DHEAD   64
#define M_ROWS  (QLEN*BSZ)          // 4096, row r = q*4 + b
#define H3      (3*NHEAD*DHEAD)     // 3072
#define SCALE   (0.125f)

// ---------------------------------------------------------------------------
// Scratch
// ---------------------------------------------------------------------------
__device__ float g_h[M_ROWS * DMODEL];            // 16 MB
__device__ float g_heads[M_ROWS * H3];            // 48 MB
__device__ float g_P[64u * 1024u * 1024u];        // 256 MB  [bn][i][j]

// ---------------------------------------------------------------------------
// Helpers
// ---------------------------------------------------------------------------
__device__ __forceinline__ uint32_t packh2(float x, float y) {
    __half2 h = __floats2half2_rn(x, y);
    return *reinterpret_cast<uint32_t*>(&h);
}

__device__ __forceinline__ void ldm_x4(uint32_t r[4], const void* p) {
    uint32_t a = (uint32_t)__cvta_generic_to_shared(p);
    asm volatile("ldmatrix.sync.aligned.m8n8.x4.shared.b16 {%0,%1,%2,%3}, [%4];"
                 : "=r"(r[0]), "=r"(r[1]), "=r"(r[2]), "=r"(r[3]) : "r"(a));
}
__device__ __forceinline__ void ldm_x2(uint32_t r[2], const void* p) {
    uint32_t a = (uint32_t)__cvta_generic_to_shared(p);
    asm volatile("ldmatrix.sync.aligned.m8n8.x2.shared.b16 {%0,%1}, [%2];"
                 : "=r"(r[0]), "=r"(r[1]) : "r"(a));
}
__device__ __forceinline__ void ldm_x2t(uint32_t r[2], const void* p) {
    uint32_t a = (uint32_t)__cvta_generic_to_shared(p);
    asm volatile("ldmatrix.sync.aligned.m8n8.x2.trans.shared.b16 {%0,%1}, [%2];"
                 : "=r"(r[0]), "=r"(r[1]) : "r"(a));
}

__device__ __forceinline__ void mma_f16(float c[4], const uint32_t a[4],
                                        const uint32_t b[2]) {
    asm volatile(
        "mma.sync.aligned.m16n8k16.row.col.f32.f16.f16.f32 "
        "{%0,%1,%2,%3}, {%4,%5,%6,%7}, {%8,%9}, {%0,%1,%2,%3};"
        : "+f"(c[0]), "+f"(c[1]), "+f"(c[2]), "+f"(c[3])
        : "r"(a[0]), "r"(a[1]), "r"(a[2]), "r"(a[3]), "r"(b[0]), "r"(b[1]));
}

// ---------------------------------------------------------------------------
// FP16 GEMM: C[M_ROWS, N] = A @ B (+bias).  BM=128 BN=128 BK=16, 256 thr.
//   AMODE 0: A[r][k] = word_emb[(r&3)][r>>2][k];  AMODE 1: row-major.
// Smem fp16, fragments via ldmatrix; mma m16n8k16.
// ---------------------------------------------------------------------------
#define AS_LD 40     // halves per As row (pad: 80B = 5*16B, conflict-free)
#define BS_LD 136    // halves per Bs row (272B = 17*16B)

template<int AMODE, int K, int N>
__global__ __launch_bounds__(256, 2)
void gemm_f16(const float* __restrict__ A, const float* __restrict__ B,
              const float* __restrict__ bias, float* __restrict__ C)
{
    __shared__ __align__(16) __half As[128 * AS_LD];
    __shared__ __align__(16) __half Bs[16 * BS_LD];

    const int t    = threadIdx.x;
    const int lane = t & 31;
    const int w    = t >> 5;
    const int wm   = w >> 2;   // 0..1 (64 rows)
    const int wn   = w & 3;    // 0..3 (32 cols)
    const int mblk = blockIdx.y;
    const int nblk = blockIdx.x;

    float acc[4][4][4];
    #pragma unroll
    for (int im = 0; im < 4; im++)
        #pragma unroll
        for (int in = 0; in < 4; in++)
            #pragma unroll
            for (int j = 0; j < 4; j++) acc[im][in][j] = 0.f;

    const int KT = K / 16;
    float4 ra[2], rb[2];

    auto loadA = [&](int kt, float4 r[2]) {
        #pragma unroll
        for (int it = 0; it < 2; it++) {
            int idx = t + it * 256;            // 0..511
            int m   = idx >> 2;                // 0..127
            int k4  = idx & 3;                 // 0..3
            int gk  = kt * 16 + k4 * 4;
            int mg  = mblk * 128 + m;
            long off;
            if (AMODE == 0)
                off = (long)((mg & 3) * QLEN + (mg >> 2)) * DEMB + gk;
            else
                off = (long)mg * K + gk;
            r[it] = *(const float4*)(A + off);
        }
    };
    auto loadB = [&](int kt, float4 r[2]) {
        #pragma unroll
        for (int it = 0; it < 2; it++) {
            int idx = t + it * 256;
            int k   = idx >> 5;
            int n4  = idx & 31;
            r[it] = *(const float4*)(B + (long)(kt * 16 + k) * N + nblk * 128 + n4 * 4);
        }
    };

    loadA(0, ra);
    loadB(0, rb);

    // ldmatrix source addresses (constant across kt)
    const __half* a_src[4];
    #pragma unroll
    for (int im = 0; im < 4; im++)
        a_src[im] = &As[(wm * 64 + im * 16 + (lane & 15)) * AS_LD + (lane >> 4) * 8];
    const __half* b_src[4];
    #pragma unroll
    for (int in = 0; in < 4; in++)
        b_src[in] = &Bs[(lane & 15) * BS_LD + wn * 32 + in * 8];

    for (int kt = 0; kt < KT; kt++) {
        __syncthreads();
        #pragma unroll
        for (int it = 0; it < 2; it++) {
            int idx = t + it * 256;
            int m = idx >> 2, k4 = idx & 3;
            uint2 v = make_uint2(packh2(ra[it].x, ra[it].y), packh2(ra[it].z, ra[it].w));
            *(uint2*)&As[m * AS_LD + k4 * 4] = v;
        }
        #pragma unroll
        for (int it = 0; it < 2; it++) {
            int idx = t + it * 256;
            int k = idx >> 5, n4 = idx & 31;
            uint2 v = make_uint2(packh2(rb[it].x, rb[it].y), packh2(rb[it].z, rb[it].w));
            *(uint2*)&Bs[k * BS_LD + n4 * 4] = v;
        }
        __syncthreads();
        if (kt + 1 < KT) { loadA(kt + 1, ra); loadB(kt + 1, rb); }

        uint32_t af[4][4], bf[4][2];
        #pragma unroll
        for (int im = 0; im < 4; im++) ldm_x4(af[im], a_src[im]);
        #pragma unroll
        for (int in = 0; in < 4; in++) ldm_x2t(bf[in], b_src[in]);
        #pragma unroll
        for (int im = 0; im < 4; im++)
            #pragma unroll
            for (int in = 0; in < 4; in++)
                mma_f16(acc[im][in], af[im], bf[in]);
    }

    #pragma unroll
    for (int im = 0; im < 4; im++) {
        #pragma unroll
        for (int in = 0; in < 4; in++) {
            int r0 = mblk * 128 + wm * 64 + im * 16 + (lane >> 2);
            int c0 = nblk * 128 + wn * 32 + in * 8 + 2 * (lane & 3);
            float b0v = 0.f, b1v = 0.f;
            if (bias) { b0v = bias[c0]; b1v = bias[c0 + 1]; }
            C[(long)r0 * N + c0]           = acc[im][in][0] + b0v;
            C[(long)r0 * N + c0 + 1]       = acc[im][in][1] + b1v;
            C[(long)(r0 + 8) * N + c0]     = acc[im][in][2] + b0v;
            C[(long)(r0 + 8) * N + c0 + 1] = acc[im][in][3] + b1v;
        }
    }
}

// ---------------------------------------------------------------------------
// Fused attention (fp16 mma). CTA = (bn, 32-row q tile), 256 threads.
// S (32x1024 fp32) in smem; exact softmax; P re-stored in place as fp16.
// ---------------------------------------------------------------------------
#define SSM_LD 1028                    // floats per S row
#define QK_LD  72                      // halves per Q/KV row (144B = 9*16B)
#define ATTN_SMEM_BYTES (32*SSM_LD*4 + (32*QK_LD + 64*QK_LD) * 2)

__global__ __launch_bounds__(256, 1)
void attn_kernel(const float* __restrict__ heads, float* __restrict__ outp,
                 float* __restrict__ Pout)
{
    extern __shared__ float sm[];
    float*  Ssm = sm;                                   // [32][1028] fp32
    __half* Ph  = reinterpret_cast<__half*>(sm);        // in-place P, stride 2056
    __half* Qsm = (__half*)(sm + 32 * SSM_LD);          // [32][72]
    __half* KV  = Qsm + 32 * QK_LD;                     // [64][72]

    const int t    = threadIdx.x;
    const int lane = t & 31;
    const int w    = t >> 5;
    const int wm   = w >> 2;   // 0..1 (16 rows each)
    const int wn   = w & 3;    // 0..3
    const int bn   = blockIdx.x;
    const int qt   = blockIdx.y;
    const int b    = bn >> 4;
    const int n    = bn & 15;

    // ---- Q tile (32 x 64) -> fp16 smem ----
    #pragma unroll
    for (int it = 0; it < 2; it++) {
        int idx = t + it * 256;
        int ir = idx >> 4, d4 = idx & 15;
        const float4 q = *(const float4*)(heads +
            (long)((qt * 32 + ir) * 4 + b) * H3 + n * 64 + d4 * 4);
        *(uint2*)&Qsm[ir * QK_LD + d4 * 4] =
            make_uint2(packh2(q.x, q.y), packh2(q.z, q.w));
    }

    float4 rkv[4];
    auto loadKV = [&](int jt, int which, float4 r[4]) {
        #pragma unroll
        for (int it = 0; it < 4; it++) {
            int idx = t + it * 256;
            int jj = idx >> 4, d4 = idx & 15;
            r[it] = *(const float4*)(heads +
                (long)((jt * 64 + jj) * 4 + b) * H3 + which * DMODEL + n * 64 + d4 * 4);
        }
    };
    auto storeKV = [&](float4 r[4]) {
        #pragma unroll
        for (int it = 0; it < 4; it++) {
            int idx = t + it * 256;
            int jj = idx >> 4, d4 = idx & 15;
            *(uint2*)&KV[jj * QK_LD + d4 * 4] =
                make_uint2(packh2(r[it].x, r[it].y), packh2(r[it].z, r[it].w));
        }
    };

    loadKV(0, 1, rkv);   // K tile 0

    // ---- S = Q K^T * SCALE ----
    for (int jt = 0; jt < 16; jt++) {
        __syncthreads();                 // KV free (and Qsm visible on iter 0)
        storeKV(rkv);
        __syncthreads();
        if (jt < 15) loadKV(jt + 1, 1, rkv);
        else         loadKV(0, 2, rkv);  // prefetch V tile 0

        float sacc[2][4] = {};
        #pragma unroll
        for (int ks = 0; ks < 4; ks++) {
            uint32_t aq[4];
            ldm_x4(aq, &Qsm[(wm * 16 + (lane & 15)) * QK_LD + ks * 16 + (lane >> 4) * 8]);
            #pragma unroll
            for (int in = 0; in < 2; in++) {
                uint32_t bk[2];
                ldm_x2(bk, &KV[(wn * 16 + in * 8 + (lane & 7)) * QK_LD +
                               ks * 16 + ((lane >> 3) & 1) * 8]);
                mma_f16(sacc[in], aq, bk);
            }
        }
        #pragma unroll
        for (int in = 0; in < 2; in++) {
            int r = wm * 16 + (lane >> 2);
            int c = jt * 64 + wn * 16 + in * 8 + 2 * (lane & 3);
            Ssm[r * SSM_LD + c]           = sacc[in][0] * SCALE;
            Ssm[r * SSM_LD + c + 1]       = sacc[in][1] * SCALE;
            Ssm[(r + 8) * SSM_LD + c]     = sacc[in][2] * SCALE;
            Ssm[(r + 8) * SSM_LD + c + 1] = sacc[in][3] * SCALE;
        }
    }
    __syncthreads();

    // ---- exact softmax; write P back as fp16 in place (+ optional gmem) ----
    for (int rr = 0; rr < 4; rr++) {
        const int r = w * 4 + rr;
        float vals[32];
        float mx = -1e30f;
        #pragma unroll
        for (int c = 0; c < 32; c++) {
            vals[c] = Ssm[r * SSM_LD + c * 32 + lane];
            mx = fmaxf(mx, vals[c]);
        }
        #pragma unroll
        for (int o = 16; o; o >>= 1) mx = fmaxf(mx, __shfl_xor_sync(0xffffffffu, mx, o));
        float s = 0.f;
        #pragma unroll
        for (int c = 0; c < 32; c++) { vals[c] = __expf(vals[c] - mx); s += vals[c]; }
        #pragma unroll
        for (int o = 16; o; o >>= 1) s += __shfl_xor_sync(0xffffffffu, s, o);
        const float inv = 1.f / s;
        const int gi = qt * 32 + r;
        #pragma unroll
        for (int c = 0; c < 32; c++) {
            float p = vals[c] * inv;
            Ph[r * (2 * SSM_LD) + c * 32 + lane] = __float2half_rn(p);
            if (Pout)
                Pout[(size_t)bn * 1048576 + (size_t)gi * 1024 + c * 32 + lane] = p;
        }
    }
    __syncthreads();

    // ---- O = P V ----
    float oacc[2][4] = {};
    for (int jt = 0; jt < 16; jt++) {
        __syncthreads();
        storeKV(rkv);                    // V tile jt
        __syncthreads();
        if (jt < 15) loadKV(jt + 1, 2, rkv);

        #pragma unroll
        for (int ks = 0; ks < 4; ks++) {
            uint32_t ap[4];
            ldm_x4(ap, Ph + (wm * 16 + (lane & 15)) * (2 * SSM_LD) +
                        jt * 64 + ks * 16 + (lane >> 4) * 8);
            #pragma unroll
            for (int in = 0; in < 2; in++) {
                uint32_t bv[2];
                ldm_x2t(bv, &KV[(ks * 16 + (lane & 15)) * QK_LD + wn * 16 + in * 8]);
                mma_f16(oacc[in], ap, bv);
            }
        }
    }

    // ---- epilogue: out[(i*4+b)][n*64 + d] ----
    #pragma unroll
    for (int in = 0; in < 2; in++) {
        int r = wm * 16 + (lane >> 2);
        int c = n * 64 + wn * 16 + in * 8 + 2 * (lane & 3);
        long gr0 = (long)((qt * 32 + r) * 4 + b);
        long gr1 = (long)((qt * 32 + r + 8) * 4 + b);
        outp[gr0 * DMODEL + c]     = oacc[in][0];
        outp[gr0 * DMODEL + c + 1] = oacc[in][1];
        outp[gr1 * DMODEL + c]     = oacc[in][2];
        outp[gr1 * DMODEL + c + 1] = oacc[in][3];
    }
}

// ---------------------------------------------------------------------------
// P scratch [bn][i][j] -> out [i][j][b][n]
// ---------------------------------------------------------------------------
__global__ __launch_bounds__(256)
void transpose_P(const float* __restrict__ P, float* __restrict__ out)
{
    __shared__ float T[64][65];
    const int jc = blockIdx.x;   // 0..15
    const int i  = blockIdx.y;   // 0..1023
    const int t  = threadIdx.x;

    #pragma unroll
    for (int it = 0; it < 4; it++) {
        int idx = t + it * 256;
        int bnv = idx >> 4, j4 = idx & 15;
        float4 v = *(const float4*)(P + (size_t)bnv * 1048576 + (size_t)i * 1024 + jc * 64 + j4 * 4);
        T[j4 * 4 + 0][bnv] = v.x;
        T[j4 * 4 + 1][bnv] = v.y;
        T[j4 * 4 + 2][bnv] = v.z;
        T[j4 * 4 + 3][bnv] = v.w;
    }
    __syncthreads();
    #pragma unroll
    for (int it = 0; it < 4; it++) {
        int idx = t + it * 256;
        int jv = idx >> 4, b4 = idx & 15;
        float4 v = make_float4(T[jv][b4 * 4], T[jv][b4 * 4 + 1],
                               T[jv][b4 * 4 + 2], T[jv][b4 * 4 + 3]);
        *(float4*)(out + (size_t)i * 65536 + (size_t)(jc * 64 + jv) * 64 + b4 * 4) = v;
    }
}

// ---------------------------------------------------------------------------
// Launch
// ---------------------------------------------------------------------------
extern "C" void kernel_launch(void* const* d_in, const int* in_sizes, int n_in,
                              void* d_out, int out_size)
{
    const float* word_emb = (const float*)d_in[0];
    const float* emb_w    = (const float*)d_in[1];
    const float* emb_b    = (const float*)d_in[2];
    const float* qkv_w0   = (const float*)d_in[3];
    const float* qkv_w1   = (const float*)d_in[4];

    float* core_out = (float*)d_out;
    float* attn_out = (float*)d_out + (size_t)M_ROWS * DMODEL;

    float *h, *heads, *P;
    cudaGetSymbolAddress((void**)&h,     g_h);
    cudaGetSymbolAddress((void**)&heads, g_heads);
    cudaGetSymbolAddress((void**)&P,     g_P);

    cudaFuncSetAttribute(attn_kernel,
                         cudaFuncAttributeMaxDynamicSharedMemorySize,
                         ATTN_SMEM_BYTES);

    gemm_f16<0, DEMB, DMODEL><<<dim3(DMODEL / 128, M_ROWS / 128), 256>>>(
        word_emb, emb_w, emb_b, h);

    gemm_f16<1, DMODEL, H3><<<dim3(H3 / 128, M_ROWS / 128), 256>>>(
        h, qkv_w0, nullptr, heads);
    attn_kernel<<<dim3(64, 32), 256, ATTN_SMEM_BYTES>>>(heads, h, nullptr);

    gemm_f16<1, DMODEL, H3><<<dim3(H3 / 128, M_ROWS / 128), 256>>>(
        h, qkv_w1, nullptr, heads);
    attn_kernel<<<dim3(64, 32), 256, ATTN_SMEM_BYTES>>>(heads, core_out, P);

    transpose_P<<<dim3(16, 1024), 256>>>(P, attn_out);
}

// round 7
// speedup vs baseline: 2.8516x; 1.6339x over previous
#include <cuda_runtime.h>
#include <cuda_fp16.h>
#include <cstdint>

// ---------------------------------------------------------------------------
// Problem constants
// ---------------------------------------------------------------------------
#define BSZ     4
#define QLEN    1024
#define DEMB    768
#define DMODEL  1024
#define NHEAD   16
#define DHEAD   64
#define M_ROWS  (QLEN*BSZ)          // 4096, row r = q*4 + b
#define H3      (3*NHEAD*DHEAD)     // 3072
#define SCALE   (0.125f)

// ---------------------------------------------------------------------------
// Scratch (fp16 everywhere)
// ---------------------------------------------------------------------------
__device__ __align__(16) __half g_we_h[BSZ*QLEN*DEMB];     // word_emb fp16
__device__ __align__(16) __half g_embw_h[DEMB*DMODEL];
__device__ __align__(16) __half g_w0_h[DMODEL*H3];
__device__ __align__(16) __half g_w1_h[DMODEL*H3];
__device__ __align__(16) __half g_h_h[M_ROWS*DMODEL];      // h (fp16)
__device__ __align__(16) __half g_heads_h[M_ROWS*H3];      // QKV (fp16)
__device__ __align__(16) __half g_P_h[64u*1024u*1024u];    // 128 MB [bn][i][j]

// ---------------------------------------------------------------------------
// Helpers
// ---------------------------------------------------------------------------
__device__ __forceinline__ void cpa16(void* dst, const void* src) {
    uint32_t d = (uint32_t)__cvta_generic_to_shared(dst);
    asm volatile("cp.async.cg.shared.global [%0], [%1], 16;" :: "r"(d), "l"(src));
}
__device__ __forceinline__ void cpcommit() {
    asm volatile("cp.async.commit_group;");
}
template<int NN> __device__ __forceinline__ void cpwait() {
    asm volatile("cp.async.wait_group %0;" :: "n"(NN));
}

__device__ __forceinline__ void ldm_x4(uint32_t r[4], const void* p) {
    uint32_t a = (uint32_t)__cvta_generic_to_shared(p);
    asm volatile("ldmatrix.sync.aligned.m8n8.x4.shared.b16 {%0,%1,%2,%3}, [%4];"
                 : "=r"(r[0]), "=r"(r[1]), "=r"(r[2]), "=r"(r[3]) : "r"(a));
}
__device__ __forceinline__ void ldm_x4t(uint32_t r[4], const void* p) {
    uint32_t a = (uint32_t)__cvta_generic_to_shared(p);
    asm volatile("ldmatrix.sync.aligned.m8n8.x4.trans.shared.b16 {%0,%1,%2,%3}, [%4];"
                 : "=r"(r[0]), "=r"(r[1]), "=r"(r[2]), "=r"(r[3]) : "r"(a));
}

__device__ __forceinline__ void mma_f16(float c[4], const uint32_t a[4],
                                        uint32_t b0, uint32_t b1) {
    asm volatile(
        "mma.sync.aligned.m16n8k16.row.col.f32.f16.f16.f32 "
        "{%0,%1,%2,%3}, {%4,%5,%6,%7}, {%8,%9}, {%0,%1,%2,%3};"
        : "+f"(c[0]), "+f"(c[1]), "+f"(c[2]), "+f"(c[3])
        : "r"(a[0]), "r"(a[1]), "r"(a[2]), "r"(a[3]), "r"(b0), "r"(b1));
}

// ---------------------------------------------------------------------------
// fp32 -> fp16 convert (vectorized)
// ---------------------------------------------------------------------------
__global__ __launch_bounds__(256)
void f32_to_f16(const float4* __restrict__ in, uint2* __restrict__ out, int n4)
{
    int i = blockIdx.x * blockDim.x + threadIdx.x;
    if (i < n4) {
        float4 v = in[i];
        __half2 lo = __floats2half2_rn(v.x, v.y);
        __half2 hi = __floats2half2_rn(v.z, v.w);
        out[i] = make_uint2(*(uint32_t*)&lo, *(uint32_t*)&hi);
    }
}

// ---------------------------------------------------------------------------
// FP16 GEMM: C[M_ROWS,N] = A@B (+bias), all fp16 in gmem, fp32 accum.
// BM=128 BN=128 BK=32, 256 threads, cp.async triple-buffered.
//   AMODE 0: A row mg -> word_emb_h row (mg&3)*QLEN + (mg>>2), stride K
//   AMODE 1: A row-major [M_ROWS,K]
// ---------------------------------------------------------------------------
#define GA_LD 40      // halves per As row (80B = 5 chunks, odd)
#define GB_LD 136     // halves per Bs row (272B = 17 chunks, odd)
#define GA_SZ (128*GA_LD)   // 5120
#define GB_SZ (32*GB_LD)    // 4352
#define GEMM_SMEM_BYTES (3*(GA_SZ+GB_SZ)*2)   // 56832

template<int AMODE, int K, int N, bool BIAS>
__global__ __launch_bounds__(256, 2)
void gemm_h(const __half* __restrict__ A, const __half* __restrict__ B,
            const float* __restrict__ bias, __half* __restrict__ C)
{
    extern __shared__ __half smp[];
    __half* As = smp;                 // 3 buffers
    __half* Bs = smp + 3 * GA_SZ;

    const int t    = threadIdx.x;
    const int lane = t & 31;
    const int w    = t >> 5;
    const int wm   = w >> 2;   // 0..1 (64 rows)
    const int wn   = w & 3;    // 0..3 (32 cols)
    const int mblk = blockIdx.y;
    const int nblk = blockIdx.x;
    const int KT   = K / 32;

    float acc[4][4][4];
    #pragma unroll
    for (int im = 0; im < 4; im++)
        #pragma unroll
        for (int g = 0; g < 4; g++)
            #pragma unroll
            for (int j = 0; j < 4; j++) acc[im][g][j] = 0.f;

    auto issue = [&](int kt) {
        __half* Ab = As + (kt % 3) * GA_SZ;
        __half* Bb = Bs + (kt % 3) * GB_SZ;
        #pragma unroll
        for (int it = 0; it < 2; it++) {
            int ca = t + it * 256;           // 0..511
            int m = ca >> 2, c = ca & 3;
            int mg = mblk * 128 + m;
            const __half* src;
            if (AMODE == 0)
                src = A + (long)((mg & 3) * QLEN + (mg >> 2)) * K + kt * 32 + c * 8;
            else
                src = A + (long)mg * K + kt * 32 + c * 8;
            cpa16(Ab + m * GA_LD + c * 8, src);
        }
        #pragma unroll
        for (int it = 0; it < 2; it++) {
            int cb = t + it * 256;
            int k = cb >> 4, c = cb & 15;
            cpa16(Bb + k * GB_LD + c * 8,
                  B + (long)(kt * 32 + k) * N + nblk * 128 + c * 8);
        }
        cpcommit();
    };

    issue(0);
    issue(1);

    for (int kt = 0; kt < KT; kt++) {
        if (kt < KT - 1) cpwait<1>(); else cpwait<0>();
        __syncthreads();
        if (kt + 2 < KT) issue(kt + 2);

        const __half* Ab = As + (kt % 3) * GA_SZ;
        const __half* Bb = Bs + (kt % 3) * GB_SZ;

        #pragma unroll
        for (int ks = 0; ks < 2; ks++) {
            uint32_t af[4][4];
            #pragma unroll
            for (int im = 0; im < 4; im++)
                ldm_x4(af[im], Ab + (wm * 64 + im * 16 + (lane & 15)) * GA_LD +
                               ks * 16 + (lane >> 4) * 8);
            uint32_t bf[2][4];
            #pragma unroll
            for (int ib = 0; ib < 2; ib++)
                ldm_x4t(bf[ib], Bb + (ks * 16 + (lane & 15)) * GB_LD +
                                wn * 32 + ib * 16 + (lane >> 4) * 8);
            #pragma unroll
            for (int im = 0; im < 4; im++) {
                mma_f16(acc[im][0], af[im], bf[0][0], bf[0][1]);
                mma_f16(acc[im][1], af[im], bf[0][2], bf[0][3]);
                mma_f16(acc[im][2], af[im], bf[1][0], bf[1][1]);
                mma_f16(acc[im][3], af[im], bf[1][2], bf[1][3]);
            }
        }
    }

    // epilogue: fp16 C
    #pragma unroll
    for (int im = 0; im < 4; im++) {
        #pragma unroll
        for (int g = 0; g < 4; g++) {
            int r0 = mblk * 128 + wm * 64 + im * 16 + (lane >> 2);
            int c0 = nblk * 128 + wn * 32 + g * 8 + 2 * (lane & 3);
            float b0v = 0.f, b1v = 0.f;
            if (BIAS) { b0v = bias[c0]; b1v = bias[c0 + 1]; }
            __half2 v0 = __floats2half2_rn(acc[im][g][0] + b0v, acc[im][g][1] + b1v);
            __half2 v1 = __floats2half2_rn(acc[im][g][2] + b0v, acc[im][g][3] + b1v);
            *(__half2*)&C[(long)r0 * N + c0]       = v0;
            *(__half2*)&C[(long)(r0 + 8) * N + c0] = v1;
        }
    }
}

// ---------------------------------------------------------------------------
// Fused attention. CTA = (bn, 64-row q tile), 256 threads, grid (64,16).
// S [64][1024] fp16 in smem (exact softmax, logits are tiny); K/V via
// cp.async triple-buffered ring; P re-stored fp16 in place; optional fp16
// P stream to gmem. LAST=true -> out fp32 (d_out) + P scratch.
// ---------------------------------------------------------------------------
#define SP_LD 1032                    // halves per S row (2064B = 129 chunks)
#define AQ_LD 72                      // halves per Q/KV row (144B = 9 chunks)
#define KV_SZ (64*AQ_LD)              // 4608 halves per buffer
#define ATTN_SMEM_BYTES ((64*SP_LD + 64*AQ_LD + 3*KV_SZ) * 2)   // 168960

template<bool LAST>
__global__ __launch_bounds__(256, 1)
void attn_h(const __half* __restrict__ heads, __half* __restrict__ outh,
            float* __restrict__ outf, __half* __restrict__ Pout)
{
    extern __shared__ __half sm[];
    __half* S  = sm;                       // [64][1032]
    __half* Q  = sm + 64 * SP_LD;          // [64][72]
    __half* KV = Q + 64 * AQ_LD;           // 3 x [64][72]

    const int t    = threadIdx.x;
    const int lane = t & 31;
    const int w    = t >> 5;
    const int wm   = w >> 1;   // 0..3 (16 rows each)
    const int wn   = w & 1;    // 0..1 (32 cols each)
    const int bn   = blockIdx.x;   // 0..63
    const int qt   = blockIdx.y;   // 0..15
    const int b    = bn >> 4;
    const int n    = bn & 15;

    auto issueKV = [&](int u) {
        int which = (u < 16) ? 1 : 2;
        int jt = u & 15;
        __half* dst = KV + (u % 3) * KV_SZ;
        #pragma unroll
        for (int it = 0; it < 2; it++) {
            int idx = t + it * 256;           // 0..511
            int jj = idx >> 3, c = idx & 7;
            cpa16(dst + jj * AQ_LD + c * 8,
                  heads + (long)((jt * 64 + jj) * 4 + b) * H3 +
                  which * DMODEL + n * 64 + c * 8);
        }
        cpcommit();
    };

    // prologue: Q + K0 (one group), K1 (second group)
    #pragma unroll
    for (int it = 0; it < 2; it++) {
        int idx = t + it * 256;
        int ir = idx >> 3, c = idx & 7;
        cpa16(Q + ir * AQ_LD + c * 8,
              heads + (long)((qt * 64 + ir) * 4 + b) * H3 + n * 64 + c * 8);
    }
    issueKV(0);
    issueKV(1);

    float oacc[4][4];
    #pragma unroll
    for (int g = 0; g < 4; g++)
        #pragma unroll
        for (int j = 0; j < 4; j++) oacc[g][j] = 0.f;

    for (int u = 0; u < 32; u++) {
        if (u < 31) cpwait<1>(); else cpwait<0>();
        __syncthreads();
        if (u + 2 < 32) issueKV(u + 2);

        if (u == 16) {
            // ---- softmax (8 rows per warp), S complete ----
            for (int rr = 0; rr < 8; rr++) {
                const int r = w * 8 + rr;
                float v[32];
                float mx = -1e30f;
                #pragma unroll
                for (int c = 0; c < 16; c++) {
                    __half2 h2 = *(__half2*)&S[r * SP_LD + c * 64 + lane * 2];
                    float2 f = __half22float2(h2);
                    v[2 * c] = f.x; v[2 * c + 1] = f.y;
                    mx = fmaxf(mx, fmaxf(f.x, f.y));
                }
                #pragma unroll
                for (int o = 16; o; o >>= 1)
                    mx = fmaxf(mx, __shfl_xor_sync(0xffffffffu, mx, o));
                float s = 0.f;
                #pragma unroll
                for (int c = 0; c < 32; c++) { v[c] = __expf(v[c] - mx); s += v[c]; }
                #pragma unroll
                for (int o = 16; o; o >>= 1) s += __shfl_xor_sync(0xffffffffu, s, o);
                const float inv = 1.f / s;
                const int gi = qt * 64 + r;
                #pragma unroll
                for (int c = 0; c < 16; c++) {
                    __half2 p = __floats2half2_rn(v[2 * c] * inv, v[2 * c + 1] * inv);
                    *(__half2*)&S[r * SP_LD + c * 64 + lane * 2] = p;
                    if (LAST)
                        *(__half2*)&Pout[(size_t)bn * 1048576 +
                                         (size_t)gi * 1024 + c * 64 + lane * 2] = p;
                }
            }
            __syncthreads();
        }

        const __half* Kb = KV + (u % 3) * KV_SZ;

        if (u < 16) {
            // ---- S[64 x 64-jtile] = Q K^T ----
            const int jt = u;
            float sacc[4][4];
            #pragma unroll
            for (int g = 0; g < 4; g++)
                #pragma unroll
                for (int j = 0; j < 4; j++) sacc[g][j] = 0.f;
            #pragma unroll
            for (int ks = 0; ks < 4; ks++) {
                uint32_t aq[4];
                ldm_x4(aq, Q + (wm * 16 + (lane & 15)) * AQ_LD +
                           ks * 16 + (lane >> 4) * 8);
                uint32_t bk0[4], bk1[4];
                ldm_x4(bk0, Kb + (wn * 32 + (lane & 15)) * AQ_LD +
                            ks * 16 + (lane >> 4) * 8);
                ldm_x4(bk1, Kb + (wn * 32 + 16 + (lane & 15)) * AQ_LD +
                            ks * 16 + (lane >> 4) * 8);
                mma_f16(sacc[0], aq, bk0[0], bk0[2]);
                mma_f16(sacc[1], aq, bk0[1], bk0[3]);
                mma_f16(sacc[2], aq, bk1[0], bk1[2]);
                mma_f16(sacc[3], aq, bk1[1], bk1[3]);
            }
            #pragma unroll
            for (int g = 0; g < 4; g++) {
                int r = wm * 16 + (lane >> 2);
                int c = jt * 64 + wn * 32 + g * 8 + 2 * (lane & 3);
                *(__half2*)&S[r * SP_LD + c] =
                    __floats2half2_rn(sacc[g][0] * SCALE, sacc[g][1] * SCALE);
                *(__half2*)&S[(r + 8) * SP_LD + c] =
                    __floats2half2_rn(sacc[g][2] * SCALE, sacc[g][3] * SCALE);
            }
        } else {
            // ---- O += P[:, jtile] V[jtile] ----
            const int jt = u - 16;
            #pragma unroll
            for (int ks = 0; ks < 4; ks++) {
                uint32_t ap[4];
                ldm_x4(ap, S + (wm * 16 + (lane & 15)) * SP_LD +
                           jt * 64 + ks * 16 + (lane >> 4) * 8);
                uint32_t bv0[4], bv1[4];
                ldm_x4t(bv0, Kb + (ks * 16 + (lane & 15)) * AQ_LD +
                             wn * 32 + (lane >> 4) * 8);
                ldm_x4t(bv1, Kb + (ks * 16 + (lane & 15)) * AQ_LD +
                             wn * 32 + 16 + (lane >> 4) * 8);
                mma_f16(oacc[0], ap, bv0[0], bv0[1]);
                mma_f16(oacc[1], ap, bv0[2], bv0[3]);
                mma_f16(oacc[2], ap, bv1[0], bv1[1]);
                mma_f16(oacc[3], ap, bv1[2], bv1[3]);
            }
        }
    }

    // ---- epilogue: out[(i*4+b)][n*64+d] ----
    #pragma unroll
    for (int g = 0; g < 4; g++) {
        int r = wm * 16 + (lane >> 2);
        int c = n * 64 + wn * 32 + g * 8 + 2 * (lane & 3);
        long gr0 = (long)((qt * 64 + r) * 4 + b);
        long gr1 = gr0 + 32;   // (r+8)*4
        if (LAST) {
            *(float2*)&outf[gr0 * DMODEL + c] = make_float2(oacc[g][0], oacc[g][1]);
            *(float2*)&outf[gr1 * DMODEL + c] = make_float2(oacc[g][2], oacc[g][3]);
        } else {
            *(__half2*)&outh[gr0 * DMODEL + c] = __floats2half2_rn(oacc[g][0], oacc[g][1]);
            *(__half2*)&outh[gr1 * DMODEL + c] = __floats2half2_rn(oacc[g][2], oacc[g][3]);
        }
    }
}

// ---------------------------------------------------------------------------
// P scratch fp16 [bn][i][j] -> out fp32 [i][j][b][n]
// ---------------------------------------------------------------------------
__global__ __launch_bounds__(256)
void transpose_P(const __half* __restrict__ P, float* __restrict__ out)
{
    __shared__ float T[64][65];
    const int jc = blockIdx.x;   // 0..15
    const int i  = blockIdx.y;   // 0..1023
    const int t  = threadIdx.x;

    #pragma unroll
    for (int it = 0; it < 2; it++) {
        int idx = t + it * 256;            // 0..511
        int bnv = idx >> 3, c = idx & 7;
        uint4 raw = *(const uint4*)(P + (size_t)bnv * 1048576 +
                                    (size_t)i * 1024 + jc * 64 + c * 8);
        const __half2* hp = (const __half2*)&raw;
        #pragma unroll
        for (int e = 0; e < 4; e++) {
            float2 f = __half22float2(hp[e]);
            T[c * 8 + 2 * e][bnv]     = f.x;
            T[c * 8 + 2 * e + 1][bnv] = f.y;
        }
    }
    __syncthreads();
    #pragma unroll
    for (int it = 0; it < 4; it++) {
        int idx = t + it * 256;
        int jv = idx >> 4, b4 = idx & 15;
        float4 v = make_float4(T[jv][b4 * 4], T[jv][b4 * 4 + 1],
                               T[jv][b4 * 4 + 2], T[jv][b4 * 4 + 3]);
        *(float4*)(out + (size_t)i * 65536 + (size_t)(jc * 64 + jv) * 64 + b4 * 4) = v;
    }
}

// ---------------------------------------------------------------------------
// Launch
// ---------------------------------------------------------------------------
extern "C" void kernel_launch(void* const* d_in, const int* in_sizes, int n_in,
                              void* d_out, int out_size)
{
    const float* word_emb = (const float*)d_in[0];
    const float* emb_w    = (const float*)d_in[1];
    const float* emb_b    = (const float*)d_in[2];
    const float* qkv_w0   = (const float*)d_in[3];
    const float* qkv_w1   = (const float*)d_in[4];

    float* core_out = (float*)d_out;
    float* attn_out = (float*)d_out + (size_t)M_ROWS * DMODEL;

    __half *we_h, *embw_h, *w0_h, *w1_h, *h_h, *heads_h, *P_h;
    cudaGetSymbolAddress((void**)&we_h,    g_we_h);
    cudaGetSymbolAddress((void**)&embw_h,  g_embw_h);
    cudaGetSymbolAddress((void**)&w0_h,    g_w0_h);
    cudaGetSymbolAddress((void**)&w1_h,    g_w1_h);
    cudaGetSymbolAddress((void**)&h_h,     g_h_h);
    cudaGetSymbolAddress((void**)&heads_h, g_heads_h);
    cudaGetSymbolAddress((void**)&P_h,     g_P_h);

    static bool attr_done = false;
    if (!attr_done) {
        cudaFuncSetAttribute(gemm_h<0, DEMB, DMODEL, true>,
            cudaFuncAttributeMaxDynamicSharedMemorySize, GEMM_SMEM_BYTES);
        cudaFuncSetAttribute(gemm_h<1, DMODEL, H3, false>,
            cudaFuncAttributeMaxDynamicSharedMemorySize, GEMM_SMEM_BYTES);
        cudaFuncSetAttribute(attn_h<false>,
            cudaFuncAttributeMaxDynamicSharedMemorySize, ATTN_SMEM_BYTES);
        cudaFuncSetAttribute(attn_h<true>,
            cudaFuncAttributeMaxDynamicSharedMemorySize, ATTN_SMEM_BYTES);
        attr_done = true;
    }

    // 0) convert inputs to fp16
    f32_to_f16<<<(BSZ*QLEN*DEMB/4 + 255)/256, 256>>>(
        (const float4*)word_emb, (uint2*)we_h, BSZ*QLEN*DEMB/4);
    f32_to_f16<<<(DEMB*DMODEL/4 + 255)/256, 256>>>(
        (const float4*)emb_w, (uint2*)embw_h, DEMB*DMODEL/4);
    f32_to_f16<<<(DMODEL*H3/4 + 255)/256, 256>>>(
        (const float4*)qkv_w0, (uint2*)w0_h, DMODEL*H3/4);
    f32_to_f16<<<(DMODEL*H3/4 + 255)/256, 256>>>(
        (const float4*)qkv_w1, (uint2*)w1_h, DMODEL*H3/4);

    // 1) h = transpose(word_emb) @ emb_w + emb_b
    gemm_h<0, DEMB, DMODEL, true><<<dim3(DMODEL/128, M_ROWS/128), 256,
        GEMM_SMEM_BYTES>>>(we_h, embw_h, emb_b, h_h);

    // 2) MHA #0
    gemm_h<1, DMODEL, H3, false><<<dim3(H3/128, M_ROWS/128), 256,
        GEMM_SMEM_BYTES>>>(h_h, w0_h, nullptr, heads_h);
    attn_h<false><<<dim3(64, 16), 256, ATTN_SMEM_BYTES>>>(
        heads_h, h_h, nullptr, nullptr);

    // 3) MHA #1 (keeps attn maps)
    gemm_h<1, DMODEL, H3, false><<<dim3(H3/128, M_ROWS/128), 256,
        GEMM_SMEM_BYTES>>>(h_h, w1_h, nullptr, heads_h);
    attn_h<true><<<dim3(64, 16), 256, ATTN_SMEM_BYTES>>>(
        heads_h, nullptr, core_out, P_h);

    // 4) attn_prob reformat [bn][i][j] -> [i][j][b][n]
    transpose_P<<<dim3(16, 1024), 256>>>(P_h, attn_out);
}